// round 1
// baseline (speedup 1.0000x reference)
#include <cuda_runtime.h>
#include <math.h>
#include <float.h>

#define BATCH 2
#define SEQ   2048
#define DIM   1024
#define NH    16
#define DH    64
#define WIN   512
#define E3    3072   // 3*NH*DH

// Scratch (allocation-free rule: device globals)
__device__ float g_qkv[BATCH * SEQ * E3];   // (B,S,3*H*DH)
__device__ float g_ctx[BATCH * SEQ * DIM];  // (B,S,H*DH)

// ---------------------------------------------------------------------------
// SGEMM: C[M,N] = A[M,K] * B[K,N], all row-major, M%128==0, N%128==0, K%8==0
// 128x128 tile, BK=8, 256 threads, 8x8 per-thread microtile (4+4 split).
// ---------------------------------------------------------------------------
__global__ __launch_bounds__(256) void sgemm_kernel(
    const float* __restrict__ A, const float* __restrict__ Bm,
    float* __restrict__ C, int M, int N, int K)
{
    __shared__ __align__(16) float As[8][128];
    __shared__ __align__(16) float Bs[8][128];

    const int tid = threadIdx.x;
    const int bx = blockIdx.x;   // N tile
    const int by = blockIdx.y;   // M tile
    const int tx = tid & 15;
    const int ty = tid >> 4;

    const float* Ab = A + (long)(by * 128) * K;
    const float* Bb = Bm + bx * 128;

    const int arow = tid >> 1;          // 0..127
    const int acol = (tid & 1) * 4;     // 0 or 4
    const int brow = tid >> 5;          // 0..7
    const int bcol = (tid & 31) * 4;    // 0..124

    float acc[8][8];
#pragma unroll
    for (int i = 0; i < 8; i++)
#pragma unroll
        for (int j = 0; j < 8; j++) acc[i][j] = 0.f;

    for (int k0 = 0; k0 < K; k0 += 8) {
        float4 a = *(const float4*)(Ab + (long)arow * K + k0 + acol);
        As[acol + 0][arow] = a.x;
        As[acol + 1][arow] = a.y;
        As[acol + 2][arow] = a.z;
        As[acol + 3][arow] = a.w;
        *(float4*)(&Bs[brow][bcol]) =
            *(const float4*)(Bb + (long)(k0 + brow) * N + bcol);
        __syncthreads();

#pragma unroll
        for (int kk = 0; kk < 8; kk++) {
            float ar[8], br[8];
            *(float4*)(ar)     = *(float4*)(&As[kk][ty * 4]);
            *(float4*)(ar + 4) = *(float4*)(&As[kk][ty * 4 + 64]);
            *(float4*)(br)     = *(float4*)(&Bs[kk][tx * 4]);
            *(float4*)(br + 4) = *(float4*)(&Bs[kk][tx * 4 + 64]);
#pragma unroll
            for (int i = 0; i < 8; i++)
#pragma unroll
                for (int j = 0; j < 8; j++)
                    acc[i][j] += ar[i] * br[j];
        }
        __syncthreads();
    }

#pragma unroll
    for (int i = 0; i < 8; i++) {
        int row = by * 128 + ((i < 4) ? (ty * 4 + i) : (64 + ty * 4 + i - 4));
        float4 v0 = make_float4(acc[i][0], acc[i][1], acc[i][2], acc[i][3]);
        float4 v1 = make_float4(acc[i][4], acc[i][5], acc[i][6], acc[i][7]);
        *(float4*)(C + (long)row * N + bx * 128 + tx * 4)      = v0;
        *(float4*)(C + (long)row * N + bx * 128 + 64 + tx * 4) = v1;
    }
}

// ---------------------------------------------------------------------------
// Sliding-window flash attention.
// Grid: (SEQ/64, NH, BATCH). Block: 256 threads.
// Per block: 64-query tile; iterate 64-key tiles over causal window of 512.
// Thread layout: row group r0=(tid/16)*4 (4 rows), col/dim group c0=(tid%16)*4.
// Online softmax state (m,l) replicated across the 16 threads of a row group
// via shfl reductions over 16 lanes.
// ---------------------------------------------------------------------------
#define LDP 68  // padded row stride (floats), keeps float4 alignment

__global__ __launch_bounds__(256) void attn_kernel(
    const float* __restrict__ qkv, float* __restrict__ ctx)
{
    extern __shared__ float sm[];
    float* Qs = sm;              // [64][LDP]  (r, d), pre-scaled
    float* Ks = Qs + 64 * LDP;   // [64][LDP]  (c, d)
    float* Vs = Ks + 64 * LDP;   // [64][LDP]  (c, d)
    float* Ps = Vs + 64 * LDP;   // [64][LDP]  (r, c)

    const int tid = threadIdx.x;
    const int i0 = blockIdx.x * 64;
    const int h  = blockIdx.y;
    const int b  = blockIdx.z;

    const float scale = 0.125f;  // DH^-0.5
    const float* qbase = qkv + (long)b * SEQ * E3 + h * DH;
    const float* kbase = qbase + DIM;
    const float* vbase = qbase + 2 * DIM;

    // Load + scale Q tile (64 rows x 64 dims)
#pragma unroll
    for (int it = 0; it < 4; it++) {
        int idx = tid + it * 256;
        int r  = idx >> 4;
        int d4 = (idx & 15) << 2;
        float4 q = *(const float4*)(qbase + (long)(i0 + r) * E3 + d4);
        q.x *= scale; q.y *= scale; q.z *= scale; q.w *= scale;
        *(float4*)(&Qs[r * LDP + d4]) = q;
    }

    const int r0 = (tid >> 4) << 2;
    const int c0 = (tid & 15) << 2;   // also output dim group

    float m[4], l[4], o[4][4];
#pragma unroll
    for (int i = 0; i < 4; i++) {
        m[i] = -FLT_MAX; l[i] = 0.f;
#pragma unroll
        for (int j = 0; j < 4; j++) o[i][j] = 0.f;
    }

    int t0 = (i0 - WIN + 1) >> 6; if (t0 < 0) t0 = 0;
    const int t1 = i0 >> 6;

    for (int t = t0; t <= t1; t++) {
        const int kt0 = t << 6;
        __syncthreads();  // previous tile's readers done with Ks/Vs/Ps

        // Load K and V tiles (coalesced, natural (c,d) layout)
#pragma unroll
        for (int it = 0; it < 4; it++) {
            int idx = tid + it * 256;
            int c  = idx >> 4;
            int d4 = (idx & 15) << 2;
            long off = (long)(kt0 + c) * E3 + d4;
            *(float4*)(&Ks[c * LDP + d4]) = *(const float4*)(kbase + off);
            *(float4*)(&Vs[c * LDP + d4]) = *(const float4*)(vbase + off);
        }
        __syncthreads();

        // S = Q K^T (4x4 microtile), reduction over d
        float s[4][4];
#pragma unroll
        for (int i = 0; i < 4; i++)
#pragma unroll
            for (int j = 0; j < 4; j++) s[i][j] = 0.f;

#pragma unroll
        for (int d4 = 0; d4 < 64; d4 += 4) {
            float4 q[4], k[4];
#pragma unroll
            for (int i = 0; i < 4; i++)
                q[i] = *(float4*)(&Qs[(r0 + i) * LDP + d4]);
#pragma unroll
            for (int j = 0; j < 4; j++)
                k[j] = *(float4*)(&Ks[(c0 + j) * LDP + d4]);
#pragma unroll
            for (int i = 0; i < 4; i++)
#pragma unroll
                for (int j = 0; j < 4; j++)
                    s[i][j] += q[i].x * k[j].x + q[i].y * k[j].y
                             + q[i].z * k[j].z + q[i].w * k[j].w;
        }

        // Sliding-window causal mask
#pragma unroll
        for (int i = 0; i < 4; i++) {
            int qi = i0 + r0 + i;
#pragma unroll
            for (int j = 0; j < 4; j++) {
                int kj = kt0 + c0 + j;
                bool ok = (kj <= qi) && (kj >= qi - (WIN - 1));
                if (!ok) s[i][j] = -FLT_MAX;
            }
        }

        // Online softmax update
        float p[4][4];
#pragma unroll
        for (int i = 0; i < 4; i++) {
            float tmax = fmaxf(fmaxf(s[i][0], s[i][1]), fmaxf(s[i][2], s[i][3]));
#pragma unroll
            for (int off = 1; off < 16; off <<= 1)
                tmax = fmaxf(tmax, __shfl_xor_sync(0xffffffffu, tmax, off));
            float mn = fmaxf(m[i], tmax);
            float alpha = __expf(m[i] - mn);   // exp(0)=1 if both -FLT_MAX
            m[i] = mn;
            float rs = 0.f;
#pragma unroll
            for (int j = 0; j < 4; j++) {
                p[i][j] = __expf(s[i][j] - mn);
                rs += p[i][j];
            }
#pragma unroll
            for (int off = 1; off < 16; off <<= 1)
                rs += __shfl_xor_sync(0xffffffffu, rs, off);
            l[i] = l[i] * alpha + rs;
#pragma unroll
            for (int j = 0; j < 4; j++) o[i][j] *= alpha;
            *(float4*)(&Ps[(r0 + i) * LDP + c0]) =
                make_float4(p[i][0], p[i][1], p[i][2], p[i][3]);
        }
        __syncthreads();

        // O += P V  (reduction over key c)
#pragma unroll 16
        for (int c = 0; c < 64; c++) {
            float4 v = *(float4*)(&Vs[c * LDP + c0]);
            float pr[4];
#pragma unroll
            for (int i = 0; i < 4; i++) pr[i] = Ps[(r0 + i) * LDP + c];
#pragma unroll
            for (int i = 0; i < 4; i++) {
                o[i][0] += pr[i] * v.x;
                o[i][1] += pr[i] * v.y;
                o[i][2] += pr[i] * v.z;
                o[i][3] += pr[i] * v.w;
            }
        }
    }

    // Epilogue: normalize and write ctx[b][s][h*DH + d]
#pragma unroll
    for (int i = 0; i < 4; i++) {
        float inv = 1.f / l[i];
        float4 res = make_float4(o[i][0] * inv, o[i][1] * inv,
                                 o[i][2] * inv, o[i][3] * inv);
        long row = (long)(b * SEQ + i0 + r0 + i);
        *(float4*)(ctx + row * DIM + h * DH + c0) = res;
    }
}

// ---------------------------------------------------------------------------
extern "C" void kernel_launch(void* const* d_in, const int* in_sizes, int n_in,
                              void* d_out, int out_size)
{
    (void)in_sizes; (void)n_in; (void)out_size;
    const float* x    = (const float*)d_in[0];  // (B,S,DIM)
    const float* Wqkv = (const float*)d_in[1];  // (DIM, 3*H*DH)
    const float* Wout = (const float*)d_in[2];  // (H*DH, DIM)
    float* out = (float*)d_out;                 // (B,S,DIM)

    float *qkv, *ctx;
    cudaGetSymbolAddress((void**)&qkv, g_qkv);
    cudaGetSymbolAddress((void**)&ctx, g_ctx);

    const int smem_attn = 4 * 64 * LDP * sizeof(float);  // 69632 B
    cudaFuncSetAttribute(attn_kernel,
                         cudaFuncAttributeMaxDynamicSharedMemorySize, smem_attn);

    const int M = BATCH * SEQ;  // 4096

    // 1) QKV projection: (4096,1024) @ (1024,3072)
    sgemm_kernel<<<dim3(E3 / 128, M / 128), 256>>>(x, Wqkv, qkv, M, E3, DIM);

    // 2) Sliding-window attention
    attn_kernel<<<dim3(SEQ / 64, NH, BATCH), 256, smem_attn>>>(qkv, ctx);

    // 3) Output projection: (4096,1024) @ (1024,1024)
    sgemm_kernel<<<dim3(DIM / 128, M / 128), 256>>>(ctx, Wout, out, M, DIM, DIM);
}

// round 2
// speedup vs baseline: 1.2050x; 1.2050x over previous
#include <cuda_runtime.h>
#include <math.h>
#include <float.h>
#include <stdint.h>

#define BATCH 2
#define SEQ   2048
#define DIM   1024
#define NH    16
#define DH    64
#define WIN   512
#define E3    3072   // 3*NH*DH

// Scratch (allocation-free rule: device globals)
__device__ float g_qkv[BATCH * SEQ * E3];   // (B,S,3*H*DH)
__device__ float g_ctx[BATCH * SEQ * DIM];  // (B,S,H*DH)

__device__ __forceinline__ uint32_t f2tf(float x) {
    uint32_t r; asm("cvt.rna.tf32.f32 %0, %1;" : "=r"(r) : "f"(x)); return r;
}

__device__ __forceinline__ void mma_tf32(float* c, const uint32_t* a, const uint32_t* b) {
    asm volatile(
        "mma.sync.aligned.m16n8k8.row.col.f32.tf32.tf32.f32 "
        "{%0,%1,%2,%3}, {%4,%5,%6,%7}, {%8,%9}, {%0,%1,%2,%3};"
        : "+f"(c[0]), "+f"(c[1]), "+f"(c[2]), "+f"(c[3])
        : "r"(a[0]), "r"(a[1]), "r"(a[2]), "r"(a[3]), "r"(b[0]), "r"(b[1]));
}

// ---------------------------------------------------------------------------
// 3xTF32 GEMM: C[M,N] = A[M,K] * B[K,N], row-major. M%128==0, N%128==0, K%16==0
// 128x128x16 block tile, 256 threads = 8 warps, warp tile 64x32 (m16n8k8 atoms)
// Error-compensated: A=Ah+Al, B=Bh+Bl (tf32 splits); C += Al*Bh + Ah*Bl + Ah*Bh
// ---------------------------------------------------------------------------
#define BM  128
#define BN  128
#define BK  16
#define LDA 20    // As row stride (floats): conflict-free frag loads (gid*20+tig)
#define LDB 136   // Bs row stride: conflict-free frag loads (8*tig+gid)

__global__ __launch_bounds__(256, 2) void gemm_tf32_kernel(
    const float* __restrict__ A, const float* __restrict__ Bm,
    float* __restrict__ C, int M, int N, int K)
{
    __shared__ __align__(16) uint32_t AsHi[BM * LDA];
    __shared__ __align__(16) uint32_t AsLo[BM * LDA];
    __shared__ __align__(16) uint32_t BsHi[BK * LDB];
    __shared__ __align__(16) uint32_t BsLo[BK * LDB];

    const int tid  = threadIdx.x;
    const int wid  = tid >> 5;
    const int lane = tid & 31;
    const int gid  = lane >> 2;
    const int tig  = lane & 3;
    const int wm   = (wid & 1) * 64;
    const int wn   = (wid >> 1) * 32;
    const int bx   = blockIdx.x;
    const int by   = blockIdx.y;

    const float* Ab = A + (long)(by * BM) * K;
    const float* Bb = Bm + bx * BN;

    float acc[4][4][4];
#pragma unroll
    for (int i = 0; i < 4; i++)
#pragma unroll
        for (int j = 0; j < 4; j++)
#pragma unroll
            for (int e = 0; e < 4; e++) acc[i][j][e] = 0.f;

    // global->smem mappings (2 float4 each for A and B per thread)
    const int a_row0 = tid >> 1;            // f = it*256+tid : row = f>>2 ... use explicit below
    (void)a_row0;

    for (int k0 = 0; k0 < K; k0 += BK) {
        // ---- global loads into registers
        float4 av[2], bv[2];
        int af_row[2], af_kc4[2], bf_k[2], bf_n4[2];
#pragma unroll
        for (int it = 0; it < 2; it++) {
            int f = it * 256 + tid;
            af_row[it] = f >> 2;              // 0..127
            af_kc4[it] = (f & 3) * 4;         // 0,4,8,12
            av[it] = *(const float4*)(Ab + (long)af_row[it] * K + k0 + af_kc4[it]);
            bf_k[it]  = f >> 5;               // 0..15
            bf_n4[it] = (f & 31) * 4;         // 0..124
            bv[it] = *(const float4*)(Bb + (long)(k0 + bf_k[it]) * N + bf_n4[it]);
        }

        __syncthreads();   // previous compute done reading smem

        // ---- split + store (vectorized uint4)
#pragma unroll
        for (int it = 0; it < 2; it++) {
            float x[4] = {av[it].x, av[it].y, av[it].z, av[it].w};
            uint32_t hi[4], lo[4];
#pragma unroll
            for (int e = 0; e < 4; e++) {
                hi[e] = f2tf(x[e]);
                lo[e] = f2tf(x[e] - __uint_as_float(hi[e]));
            }
            int off = af_row[it] * LDA + af_kc4[it];
            *(uint4*)(&AsHi[off]) = make_uint4(hi[0], hi[1], hi[2], hi[3]);
            *(uint4*)(&AsLo[off]) = make_uint4(lo[0], lo[1], lo[2], lo[3]);

            float y[4] = {bv[it].x, bv[it].y, bv[it].z, bv[it].w};
#pragma unroll
            for (int e = 0; e < 4; e++) {
                hi[e] = f2tf(y[e]);
                lo[e] = f2tf(y[e] - __uint_as_float(hi[e]));
            }
            off = bf_k[it] * LDB + bf_n4[it];
            *(uint4*)(&BsHi[off]) = make_uint4(hi[0], hi[1], hi[2], hi[3]);
            *(uint4*)(&BsLo[off]) = make_uint4(lo[0], lo[1], lo[2], lo[3]);
        }
        __syncthreads();

        // ---- compute: 2 k-steps of 8
#pragma unroll
        for (int ks = 0; ks < 2; ks++) {
            const int kk = ks * 8;
            uint32_t bh[4][2], bl[4][2];
#pragma unroll
            for (int bn = 0; bn < 4; bn++) {
                int n = wn + bn * 8 + gid;
                bh[bn][0] = BsHi[(kk + tig) * LDB + n];
                bh[bn][1] = BsHi[(kk + tig + 4) * LDB + n];
                bl[bn][0] = BsLo[(kk + tig) * LDB + n];
                bl[bn][1] = BsLo[(kk + tig + 4) * LDB + n];
            }
#pragma unroll
            for (int am = 0; am < 4; am++) {
                int m = wm + am * 16 + gid;
                uint32_t ah[4], al[4];
                ah[0] = AsHi[m * LDA + kk + tig];
                ah[1] = AsHi[(m + 8) * LDA + kk + tig];
                ah[2] = AsHi[m * LDA + kk + tig + 4];
                ah[3] = AsHi[(m + 8) * LDA + kk + tig + 4];
                al[0] = AsLo[m * LDA + kk + tig];
                al[1] = AsLo[(m + 8) * LDA + kk + tig];
                al[2] = AsLo[m * LDA + kk + tig + 4];
                al[3] = AsLo[(m + 8) * LDA + kk + tig + 4];
#pragma unroll
                for (int bn = 0; bn < 4; bn++) {
                    mma_tf32(acc[am][bn], al, bh[bn]);   // Al*Bh
                    mma_tf32(acc[am][bn], ah, bl[bn]);   // Ah*Bl
                    mma_tf32(acc[am][bn], ah, bh[bn]);   // Ah*Bh
                }
            }
        }
    }

    // ---- epilogue
#pragma unroll
    for (int am = 0; am < 4; am++) {
#pragma unroll
        for (int bn = 0; bn < 4; bn++) {
            int row = by * BM + wm + am * 16 + gid;
            int col = bx * BN + wn + bn * 8 + tig * 2;
            *(float2*)(C + (long)row * N + col) =
                make_float2(acc[am][bn][0], acc[am][bn][1]);
            *(float2*)(C + (long)(row + 8) * N + col) =
                make_float2(acc[am][bn][2], acc[am][bn][3]);
        }
    }
}

// ---------------------------------------------------------------------------
// Sliding-window flash attention (unchanged from R1 baseline).
// ---------------------------------------------------------------------------
#define LDP 68  // padded row stride (floats)

__global__ __launch_bounds__(256) void attn_kernel(
    const float* __restrict__ qkv, float* __restrict__ ctx)
{
    extern __shared__ float sm[];
    float* Qs = sm;              // [64][LDP]
    float* Ks = Qs + 64 * LDP;
    float* Vs = Ks + 64 * LDP;
    float* Ps = Vs + 64 * LDP;

    const int tid = threadIdx.x;
    const int i0 = blockIdx.x * 64;
    const int h  = blockIdx.y;
    const int b  = blockIdx.z;

    const float scale = 0.125f;
    const float* qbase = qkv + (long)b * SEQ * E3 + h * DH;
    const float* kbase = qbase + DIM;
    const float* vbase = qbase + 2 * DIM;

#pragma unroll
    for (int it = 0; it < 4; it++) {
        int idx = tid + it * 256;
        int r  = idx >> 4;
        int d4 = (idx & 15) << 2;
        float4 q = *(const float4*)(qbase + (long)(i0 + r) * E3 + d4);
        q.x *= scale; q.y *= scale; q.z *= scale; q.w *= scale;
        *(float4*)(&Qs[r * LDP + d4]) = q;
    }

    const int r0 = (tid >> 4) << 2;
    const int c0 = (tid & 15) << 2;

    float m[4], l[4], o[4][4];
#pragma unroll
    for (int i = 0; i < 4; i++) {
        m[i] = -FLT_MAX; l[i] = 0.f;
#pragma unroll
        for (int j = 0; j < 4; j++) o[i][j] = 0.f;
    }

    int t0 = (i0 - WIN + 1) >> 6; if (t0 < 0) t0 = 0;
    const int t1 = i0 >> 6;

    for (int t = t0; t <= t1; t++) {
        const int kt0 = t << 6;
        __syncthreads();

#pragma unroll
        for (int it = 0; it < 4; it++) {
            int idx = tid + it * 256;
            int c  = idx >> 4;
            int d4 = (idx & 15) << 2;
            long off = (long)(kt0 + c) * E3 + d4;
            *(float4*)(&Ks[c * LDP + d4]) = *(const float4*)(kbase + off);
            *(float4*)(&Vs[c * LDP + d4]) = *(const float4*)(vbase + off);
        }
        __syncthreads();

        float s[4][4];
#pragma unroll
        for (int i = 0; i < 4; i++)
#pragma unroll
            for (int j = 0; j < 4; j++) s[i][j] = 0.f;

#pragma unroll
        for (int d4 = 0; d4 < 64; d4 += 4) {
            float4 q[4], k[4];
#pragma unroll
            for (int i = 0; i < 4; i++)
                q[i] = *(float4*)(&Qs[(r0 + i) * LDP + d4]);
#pragma unroll
            for (int j = 0; j < 4; j++)
                k[j] = *(float4*)(&Ks[(c0 + j) * LDP + d4]);
#pragma unroll
            for (int i = 0; i < 4; i++)
#pragma unroll
                for (int j = 0; j < 4; j++)
                    s[i][j] += q[i].x * k[j].x + q[i].y * k[j].y
                             + q[i].z * k[j].z + q[i].w * k[j].w;
        }

#pragma unroll
        for (int i = 0; i < 4; i++) {
            int qi = i0 + r0 + i;
#pragma unroll
            for (int j = 0; j < 4; j++) {
                int kj = kt0 + c0 + j;
                bool ok = (kj <= qi) && (kj >= qi - (WIN - 1));
                if (!ok) s[i][j] = -FLT_MAX;
            }
        }

        float p[4][4];
#pragma unroll
        for (int i = 0; i < 4; i++) {
            float tmax = fmaxf(fmaxf(s[i][0], s[i][1]), fmaxf(s[i][2], s[i][3]));
#pragma unroll
            for (int off = 1; off < 16; off <<= 1)
                tmax = fmaxf(tmax, __shfl_xor_sync(0xffffffffu, tmax, off));
            float mn = fmaxf(m[i], tmax);
            float alpha = __expf(m[i] - mn);
            m[i] = mn;
            float rs = 0.f;
#pragma unroll
            for (int j = 0; j < 4; j++) {
                p[i][j] = __expf(s[i][j] - mn);
                rs += p[i][j];
            }
#pragma unroll
            for (int off = 1; off < 16; off <<= 1)
                rs += __shfl_xor_sync(0xffffffffu, rs, off);
            l[i] = l[i] * alpha + rs;
#pragma unroll
            for (int j = 0; j < 4; j++) o[i][j] *= alpha;
            *(float4*)(&Ps[(r0 + i) * LDP + c0]) =
                make_float4(p[i][0], p[i][1], p[i][2], p[i][3]);
        }
        __syncthreads();

#pragma unroll 16
        for (int c = 0; c < 64; c++) {
            float4 v = *(float4*)(&Vs[c * LDP + c0]);
            float pr[4];
#pragma unroll
            for (int i = 0; i < 4; i++) pr[i] = Ps[(r0 + i) * LDP + c];
#pragma unroll
            for (int i = 0; i < 4; i++) {
                o[i][0] += pr[i] * v.x;
                o[i][1] += pr[i] * v.y;
                o[i][2] += pr[i] * v.z;
                o[i][3] += pr[i] * v.w;
            }
        }
    }

#pragma unroll
    for (int i = 0; i < 4; i++) {
        float inv = 1.f / l[i];
        float4 res = make_float4(o[i][0] * inv, o[i][1] * inv,
                                 o[i][2] * inv, o[i][3] * inv);
        long row = (long)(b * SEQ + i0 + r0 + i);
        *(float4*)(ctx + row * DIM + h * DH + c0) = res;
    }
}

// ---------------------------------------------------------------------------
extern "C" void kernel_launch(void* const* d_in, const int* in_sizes, int n_in,
                              void* d_out, int out_size)
{
    (void)in_sizes; (void)n_in; (void)out_size;
    const float* x    = (const float*)d_in[0];  // (B,S,DIM)
    const float* Wqkv = (const float*)d_in[1];  // (DIM, 3*H*DH)
    const float* Wout = (const float*)d_in[2];  // (H*DH, DIM)
    float* out = (float*)d_out;                 // (B,S,DIM)

    float *qkv, *ctx;
    cudaGetSymbolAddress((void**)&qkv, g_qkv);
    cudaGetSymbolAddress((void**)&ctx, g_ctx);

    const int smem_attn = 4 * 64 * LDP * sizeof(float);  // 69632 B
    cudaFuncSetAttribute(attn_kernel,
                         cudaFuncAttributeMaxDynamicSharedMemorySize, smem_attn);

    const int M = BATCH * SEQ;  // 4096

    // 1) QKV projection: (4096,1024) @ (1024,3072)
    gemm_tf32_kernel<<<dim3(E3 / BN, M / BM), 256>>>(x, Wqkv, qkv, M, E3, DIM);

    // 2) Sliding-window attention
    attn_kernel<<<dim3(SEQ / 64, NH, BATCH), 256, smem_attn>>>(qkv, ctx);

    // 3) Output projection: (4096,1024) @ (1024,1024)
    gemm_tf32_kernel<<<dim3(DIM / BN, M / BM), 256>>>(ctx, Wout, out, M, DIM, DIM);
}

// round 3
// speedup vs baseline: 2.8933x; 2.4011x over previous
#include <cuda_runtime.h>
#include <cuda_bf16.h>
#include <math.h>
#include <float.h>
#include <stdint.h>

#define BATCH 2
#define SEQ   2048
#define DIM   1024
#define NH    16
#define DH    64
#define WIN   512
#define E3    3072   // 3*NH*DH

// Scratch (allocation-free rule: device globals)
__device__ float g_qkv[BATCH * SEQ * E3];   // (B,S,3*H*DH)
__device__ float g_ctx[BATCH * SEQ * DIM];  // (B,S,H*DH)

// pack two floats (x -> low half, y -> high half) as bf16x2
__device__ __forceinline__ uint32_t pack_bf16(float lo, float hi) {
    uint32_t r;
    asm("cvt.rn.bf16x2.f32 %0, %1, %2;" : "=r"(r) : "f"(hi), "f"(lo));
    return r;
}

// split (x,y) into hi bf16 pair + lo residual bf16 pair
__device__ __forceinline__ void split_pair(float x, float y, uint32_t& hi, uint32_t& lo) {
    hi = pack_bf16(x, y);
    float xh = __uint_as_float(hi << 16);
    float yh = __uint_as_float(hi & 0xFFFF0000u);
    lo = pack_bf16(x - xh, y - yh);
}

__device__ __forceinline__ void mma_bf16(float* c, const uint32_t* a, const uint32_t* b) {
    asm volatile(
        "mma.sync.aligned.m16n8k16.row.col.f32.bf16.bf16.f32 "
        "{%0,%1,%2,%3}, {%4,%5,%6,%7}, {%8,%9}, {%0,%1,%2,%3};"
        : "+f"(c[0]), "+f"(c[1]), "+f"(c[2]), "+f"(c[3])
        : "r"(a[0]), "r"(a[1]), "r"(a[2]), "r"(a[3]), "r"(b[0]), "r"(b[1]));
}

// ---------------------------------------------------------------------------
// 3xBF16 GEMM: C[M,N] = A[M,K]*B[K,N]. Block 128x128xBK16, 128 thr = 4 warps,
// warp tile 64x64. Double-buffered smem. A/B split into bf16 hi+lo; 3 passes.
// Smem packs bf16 PAIRS along k into uint32.
// ---------------------------------------------------------------------------
#define GLDA 12    // uint32 stride for As rows (8 used + 4 pad) -> conflict-free frags
#define GLDB 136   // uint32 stride for Bs rows (128 used + 8 pad)
#define G_ASZ (128 * GLDA)          // 1536 uints
#define G_BSZ (8 * GLDB)            // 1088 uints
#define G_BUF (2 * (G_ASZ + G_BSZ)) // per double-buffer half, uints

__global__ __launch_bounds__(128) void gemm_bf16x3(
    const float* __restrict__ A, const float* __restrict__ Bm,
    float* __restrict__ C, int M, int N, int K)
{
    extern __shared__ uint32_t smu[];
    const int tid  = threadIdx.x;
    const int wid  = tid >> 5;
    const int lane = tid & 31;
    const int gid  = lane >> 2;
    const int tig  = lane & 3;
    const int wm   = (wid & 1) * 64;
    const int wn   = (wid >> 1) * 64;

    const float* Ab = A + (long)(blockIdx.y * 128) * K;
    const float* Bb = Bm + blockIdx.x * 128;

    float acc[4][8][4] = {};

    float4 sa[4];
    float4 sb0[2], sb1[2];

    // ---- stage loaders / storers
    auto load_stage = [&](int k0) {
#pragma unroll
        for (int it = 0; it < 4; it++) {
            int f = it * 128 + tid;
            sa[it] = *(const float4*)(Ab + (long)(f >> 2) * K + k0 + (f & 3) * 4);
        }
#pragma unroll
        for (int u = 0; u < 2; u++) {
            int g = u * 128 + tid;
            int m2 = g >> 5, n4 = (g & 31) * 4;
            sb0[u] = *(const float4*)(Bb + (long)(k0 + 2 * m2) * N + n4);
            sb1[u] = *(const float4*)(Bb + (long)(k0 + 2 * m2 + 1) * N + n4);
        }
    };
    auto store_stage = [&](uint32_t* buf) {
        uint32_t* AsHi = buf;
        uint32_t* AsLo = buf + G_ASZ;
        uint32_t* BsHi = buf + 2 * G_ASZ;
        uint32_t* BsLo = BsHi + G_BSZ;
#pragma unroll
        for (int it = 0; it < 4; it++) {
            int f = it * 128 + tid;
            int row = f >> 2, kc = (f & 3) * 4;
            uint32_t h0, l0, h1, l1;
            split_pair(sa[it].x, sa[it].y, h0, l0);
            split_pair(sa[it].z, sa[it].w, h1, l1);
            int off = row * GLDA + (kc >> 1);
            *(uint2*)(&AsHi[off]) = make_uint2(h0, h1);
            *(uint2*)(&AsLo[off]) = make_uint2(l0, l1);
        }
#pragma unroll
        for (int u = 0; u < 2; u++) {
            int g = u * 128 + tid;
            int m2 = g >> 5, n4 = (g & 31) * 4;
            uint32_t hh[4], ll[4];
            split_pair(sb0[u].x, sb1[u].x, hh[0], ll[0]);
            split_pair(sb0[u].y, sb1[u].y, hh[1], ll[1]);
            split_pair(sb0[u].z, sb1[u].z, hh[2], ll[2]);
            split_pair(sb0[u].w, sb1[u].w, hh[3], ll[3]);
            *(uint4*)(&BsHi[m2 * GLDB + n4]) = make_uint4(hh[0], hh[1], hh[2], hh[3]);
            *(uint4*)(&BsLo[m2 * GLDB + n4]) = make_uint4(ll[0], ll[1], ll[2], ll[3]);
        }
    };
    auto compute = [&](const uint32_t* buf) {
        const uint32_t* AsHi = buf;
        const uint32_t* AsLo = buf + G_ASZ;
        const uint32_t* BsHi = buf + 2 * G_ASZ;
        const uint32_t* BsLo = BsHi + G_BSZ;
        uint32_t bh[8][2], bl[8][2];
#pragma unroll
        for (int bn = 0; bn < 8; bn++) {
            int n = wn + bn * 8 + gid;
            bh[bn][0] = BsHi[tig * GLDB + n];
            bh[bn][1] = BsHi[(4 + tig) * GLDB + n];
            bl[bn][0] = BsLo[tig * GLDB + n];
            bl[bn][1] = BsLo[(4 + tig) * GLDB + n];
        }
#pragma unroll
        for (int am = 0; am < 4; am++) {
            int m = wm + am * 16 + gid;
            uint32_t ah[4], al[4];
            ah[0] = AsHi[m * GLDA + tig];
            ah[1] = AsHi[(m + 8) * GLDA + tig];
            ah[2] = AsHi[m * GLDA + 4 + tig];
            ah[3] = AsHi[(m + 8) * GLDA + 4 + tig];
            al[0] = AsLo[m * GLDA + tig];
            al[1] = AsLo[(m + 8) * GLDA + tig];
            al[2] = AsLo[m * GLDA + 4 + tig];
            al[3] = AsLo[(m + 8) * GLDA + 4 + tig];
#pragma unroll
            for (int bn = 0; bn < 8; bn++) {
                mma_bf16(acc[am][bn], al, bh[bn]);   // Al*Bh
                mma_bf16(acc[am][bn], ah, bl[bn]);   // Ah*Bl
                mma_bf16(acc[am][bn], ah, bh[bn]);   // Ah*Bh
            }
        }
    };

    load_stage(0);
    store_stage(smu);
    __syncthreads();

    const int nT = K / 16;
    for (int t = 0; t < nT; t++) {
        if (t + 1 < nT) load_stage((t + 1) * 16);
        compute(smu + (t & 1) * G_BUF);
        if (t + 1 < nT) store_stage(smu + ((t + 1) & 1) * G_BUF);
        __syncthreads();
    }

#pragma unroll
    for (int am = 0; am < 4; am++)
#pragma unroll
        for (int bn = 0; bn < 8; bn++) {
            int row = blockIdx.y * 128 + wm + am * 16 + gid;
            int col = blockIdx.x * 128 + wn + bn * 8 + tig * 2;
            *(float2*)(C + (long)row * N + col) =
                make_float2(acc[am][bn][0], acc[am][bn][1]);
            *(float2*)(C + (long)(row + 8) * N + col) =
                make_float2(acc[am][bn][2], acc[am][bn][3]);
        }
}

// ---------------------------------------------------------------------------
// Sliding-window flash attention on tensor cores (bf16 hi/lo, 3-pass).
// Grid (SEQ/128, NH, BATCH), 128 threads = 4 warps, warp = 32 q-rows.
// Key tile 64. Q fragments live in registers for the whole block.
// ---------------------------------------------------------------------------
#define ALDK 36   // Ks32 row stride (32 used + 4 pad)
#define ALDV 72   // Vs32 row stride (64 used + 8 pad)

__global__ __launch_bounds__(128) void attn_bf16x3(
    const float* __restrict__ qkv, float* __restrict__ ctx)
{
    __shared__ uint32_t KsHi[64 * ALDK], KsLo[64 * ALDK];
    __shared__ uint32_t VsHi[32 * ALDV], VsLo[32 * ALDV];

    const int tid  = threadIdx.x;
    const int wid  = tid >> 5;
    const int lane = tid & 31;
    const int gid  = lane >> 2;
    const int tig  = lane & 3;
    const int i0   = blockIdx.x * 128;
    const int h    = blockIdx.y;
    const int b    = blockIdx.z;

    const float* base = qkv + (long)b * SEQ * E3 + h * DH;
    const float* Kb = base + DIM;
    const float* Vb = base + 2 * DIM;

    // Q fragments (pre-scaled by DH^-0.5), hi/lo split
    uint32_t qh[2][4][4], ql[2][4][4];
#pragma unroll
    for (int am = 0; am < 2; am++) {
        int r0 = i0 + wid * 32 + am * 16 + gid;
#pragma unroll
        for (int s = 0; s < 4; s++) {
            float2 x0 = *(const float2*)(base + (long)r0 * E3 + s * 16 + 2 * tig);
            float2 x1 = *(const float2*)(base + (long)(r0 + 8) * E3 + s * 16 + 2 * tig);
            float2 x2 = *(const float2*)(base + (long)r0 * E3 + s * 16 + 8 + 2 * tig);
            float2 x3 = *(const float2*)(base + (long)(r0 + 8) * E3 + s * 16 + 8 + 2 * tig);
            split_pair(x0.x * 0.125f, x0.y * 0.125f, qh[am][s][0], ql[am][s][0]);
            split_pair(x1.x * 0.125f, x1.y * 0.125f, qh[am][s][1], ql[am][s][1]);
            split_pair(x2.x * 0.125f, x2.y * 0.125f, qh[am][s][2], ql[am][s][2]);
            split_pair(x3.x * 0.125f, x3.y * 0.125f, qh[am][s][3], ql[am][s][3]);
        }
    }

    float mrow[2][2], lrow[2][2], o[2][8][4] = {};
#pragma unroll
    for (int am = 0; am < 2; am++) {
        mrow[am][0] = -FLT_MAX; mrow[am][1] = -FLT_MAX;
        lrow[am][0] = 0.f;      lrow[am][1] = 0.f;
    }

    int t0 = (i0 - WIN + 1) >> 6; if (t0 < 0) t0 = 0;
    const int t1 = (i0 + 127) >> 6;

    for (int t = t0; t <= t1; t++) {
        const int kt0 = t << 6;
        __syncthreads();   // previous iteration's readers done

        // ---- load K tile (pack bf16 pairs along dh)
#pragma unroll
        for (int it = 0; it < 8; it++) {
            int f = it * 128 + tid;
            int row = f >> 4, d4 = (f & 15) * 4;
            float4 kv = *(const float4*)(Kb + (long)(kt0 + row) * E3 + d4);
            uint32_t h0, l0, h1, l1;
            split_pair(kv.x, kv.y, h0, l0);
            split_pair(kv.z, kv.w, h1, l1);
            int off = row * ALDK + (d4 >> 1);
            *(uint2*)(&KsHi[off]) = make_uint2(h0, h1);
            *(uint2*)(&KsLo[off]) = make_uint2(l0, l1);
        }
        // ---- load V tile (pack bf16 pairs along key)
#pragma unroll
        for (int u = 0; u < 4; u++) {
            int g = u * 128 + tid;
            int m2 = g >> 4, n4 = (g & 15) * 4;
            float4 v0 = *(const float4*)(Vb + (long)(kt0 + 2 * m2) * E3 + n4);
            float4 v1 = *(const float4*)(Vb + (long)(kt0 + 2 * m2 + 1) * E3 + n4);
            uint32_t hh[4], ll[4];
            split_pair(v0.x, v1.x, hh[0], ll[0]);
            split_pair(v0.y, v1.y, hh[1], ll[1]);
            split_pair(v0.z, v1.z, hh[2], ll[2]);
            split_pair(v0.w, v1.w, hh[3], ll[3]);
            *(uint4*)(&VsHi[m2 * ALDV + n4]) = make_uint4(hh[0], hh[1], hh[2], hh[3]);
            *(uint4*)(&VsLo[m2 * ALDV + n4]) = make_uint4(ll[0], ll[1], ll[2], ll[3]);
        }
        __syncthreads();

        // ---- S = Q K^T
        float s[2][8][4] = {};
#pragma unroll
        for (int bn = 0; bn < 8; bn++) {
            int n = bn * 8 + gid;
#pragma unroll
            for (int ks = 0; ks < 4; ks++) {
                uint32_t kh[2], kl[2];
                kh[0] = KsHi[n * ALDK + ks * 8 + tig];
                kh[1] = KsHi[n * ALDK + ks * 8 + 4 + tig];
                kl[0] = KsLo[n * ALDK + ks * 8 + tig];
                kl[1] = KsLo[n * ALDK + ks * 8 + 4 + tig];
#pragma unroll
                for (int am = 0; am < 2; am++) {
                    mma_bf16(s[am][bn], ql[am][ks], kh);
                    mma_bf16(s[am][bn], qh[am][ks], kl);
                    mma_bf16(s[am][bn], qh[am][ks], kh);
                }
            }
        }

        // ---- mask + online softmax (rows gid / gid+8 per am)
#pragma unroll
        for (int am = 0; am < 2; am++) {
            int qi0 = i0 + wid * 32 + am * 16 + gid;
            int qi1 = qi0 + 8;
#pragma unroll
            for (int bn = 0; bn < 8; bn++) {
                int c0 = kt0 + bn * 8 + 2 * tig, c1 = c0 + 1;
                if (c0 > qi0 || c0 < qi0 - (WIN - 1)) s[am][bn][0] = -FLT_MAX;
                if (c1 > qi0 || c1 < qi0 - (WIN - 1)) s[am][bn][1] = -FLT_MAX;
                if (c0 > qi1 || c0 < qi1 - (WIN - 1)) s[am][bn][2] = -FLT_MAX;
                if (c1 > qi1 || c1 < qi1 - (WIN - 1)) s[am][bn][3] = -FLT_MAX;
            }
            float mx0 = -FLT_MAX, mx1 = -FLT_MAX;
#pragma unroll
            for (int bn = 0; bn < 8; bn++) {
                mx0 = fmaxf(mx0, fmaxf(s[am][bn][0], s[am][bn][1]));
                mx1 = fmaxf(mx1, fmaxf(s[am][bn][2], s[am][bn][3]));
            }
            mx0 = fmaxf(mx0, __shfl_xor_sync(0xffffffffu, mx0, 1));
            mx0 = fmaxf(mx0, __shfl_xor_sync(0xffffffffu, mx0, 2));
            mx1 = fmaxf(mx1, __shfl_xor_sync(0xffffffffu, mx1, 1));
            mx1 = fmaxf(mx1, __shfl_xor_sync(0xffffffffu, mx1, 2));
            float mn0 = fmaxf(mrow[am][0], mx0);
            float mn1 = fmaxf(mrow[am][1], mx1);
            float a0 = __expf(mrow[am][0] - mn0);
            float a1 = __expf(mrow[am][1] - mn1);
            mrow[am][0] = mn0; mrow[am][1] = mn1;
            float rs0 = 0.f, rs1 = 0.f;
#pragma unroll
            for (int bn = 0; bn < 8; bn++) {
                s[am][bn][0] = __expf(s[am][bn][0] - mn0);
                s[am][bn][1] = __expf(s[am][bn][1] - mn0);
                s[am][bn][2] = __expf(s[am][bn][2] - mn1);
                s[am][bn][3] = __expf(s[am][bn][3] - mn1);
                rs0 += s[am][bn][0] + s[am][bn][1];
                rs1 += s[am][bn][2] + s[am][bn][3];
            }
            rs0 += __shfl_xor_sync(0xffffffffu, rs0, 1);
            rs0 += __shfl_xor_sync(0xffffffffu, rs0, 2);
            rs1 += __shfl_xor_sync(0xffffffffu, rs1, 1);
            rs1 += __shfl_xor_sync(0xffffffffu, rs1, 2);
            lrow[am][0] = lrow[am][0] * a0 + rs0;
            lrow[am][1] = lrow[am][1] * a1 + rs1;
#pragma unroll
            for (int bn = 0; bn < 8; bn++) {
                o[am][bn][0] *= a0; o[am][bn][1] *= a0;
                o[am][bn][2] *= a1; o[am][bn][3] *= a1;
            }
        }

        // ---- build P fragments (hi/lo) directly from S accumulators
        uint32_t pf[2][4][4], pg[2][4][4];
#pragma unroll
        for (int am = 0; am < 2; am++)
#pragma unroll
            for (int ks = 0; ks < 4; ks++) {
                split_pair(s[am][2 * ks][0],     s[am][2 * ks][1],     pf[am][ks][0], pg[am][ks][0]);
                split_pair(s[am][2 * ks][2],     s[am][2 * ks][3],     pf[am][ks][1], pg[am][ks][1]);
                split_pair(s[am][2 * ks + 1][0], s[am][2 * ks + 1][1], pf[am][ks][2], pg[am][ks][2]);
                split_pair(s[am][2 * ks + 1][2], s[am][2 * ks + 1][3], pf[am][ks][3], pg[am][ks][3]);
            }

        // ---- O += P V
#pragma unroll
        for (int bn = 0; bn < 8; bn++) {
            int n = bn * 8 + gid;
#pragma unroll
            for (int ks = 0; ks < 4; ks++) {
                uint32_t vh[2], vl[2];
                vh[0] = VsHi[(ks * 8 + tig) * ALDV + n];
                vh[1] = VsHi[(ks * 8 + 4 + tig) * ALDV + n];
                vl[0] = VsLo[(ks * 8 + tig) * ALDV + n];
                vl[1] = VsLo[(ks * 8 + 4 + tig) * ALDV + n];
#pragma unroll
                for (int am = 0; am < 2; am++) {
                    mma_bf16(o[am][bn], pg[am][ks], vh);
                    mma_bf16(o[am][bn], pf[am][ks], vl);
                    mma_bf16(o[am][bn], pf[am][ks], vh);
                }
            }
        }
    }

    // ---- epilogue
#pragma unroll
    for (int am = 0; am < 2; am++) {
        float inv0 = 1.f / lrow[am][0];
        float inv1 = 1.f / lrow[am][1];
        long r0 = (long)(b * SEQ + i0 + wid * 32 + am * 16 + gid);
#pragma unroll
        for (int bn = 0; bn < 8; bn++) {
            int col = h * DH + bn * 8 + 2 * tig;
            *(float2*)(ctx + r0 * DIM + col) =
                make_float2(o[am][bn][0] * inv0, o[am][bn][1] * inv0);
            *(float2*)(ctx + (r0 + 8) * DIM + col) =
                make_float2(o[am][bn][2] * inv1, o[am][bn][3] * inv1);
        }
    }
}

// ---------------------------------------------------------------------------
extern "C" void kernel_launch(void* const* d_in, const int* in_sizes, int n_in,
                              void* d_out, int out_size)
{
    (void)in_sizes; (void)n_in; (void)out_size;
    const float* x    = (const float*)d_in[0];  // (B,S,DIM)
    const float* Wqkv = (const float*)d_in[1];  // (DIM, 3*H*DH)
    const float* Wout = (const float*)d_in[2];  // (H*DH, DIM)
    float* out = (float*)d_out;                 // (B,S,DIM)

    float *qkv, *ctx;
    cudaGetSymbolAddress((void**)&qkv, g_qkv);
    cudaGetSymbolAddress((void**)&ctx, g_ctx);

    const int M = BATCH * SEQ;  // 4096
    const int gemm_smem = 2 * G_BUF * sizeof(uint32_t);  // 41984 B

    // 1) QKV projection: (4096,1024) @ (1024,3072)
    gemm_bf16x3<<<dim3(E3 / 128, M / 128), 128, gemm_smem>>>(x, Wqkv, qkv, M, E3, DIM);

    // 2) Sliding-window attention (tensor cores)
    attn_bf16x3<<<dim3(SEQ / 128, NH, BATCH), 128>>>(qkv, ctx);

    // 3) Output projection: (4096,1024) @ (1024,1024)
    gemm_bf16x3<<<dim3(DIM / 128, M / 128), 128, gemm_smem>>>(ctx, Wout, out, M, DIM, DIM);
}